// round 2
// baseline (speedup 1.0000x reference)
#include <cuda_runtime.h>
#include <cuda_fp16.h>
#include <cstdint>

#define DI __device__ __forceinline__

// ---------------- problem constants ----------------
namespace {
constexpr int I_DIM   = 512;
constexpr int O_DIM   = 512;
constexpr int NDEG    = 8;              // degrees 1..8 in the GEMM; d=0 -> bias
constexpr int KTOT    = NDEG * I_DIM;   // 4096
constexpr int M_TILE  = 128;
constexpr int N_TILE  = 128;
constexpr int KBLK    = 64;             // one i-block
constexpr int NUM_IB  = I_DIM / KBLK;   // 8
constexpr int THREADS = 256;            // 8 warps: warp_m = wid&3 (32 rows), warp_n = wid>>2 (64 cols)

constexpr float B_SCALE   = 512.0f;
constexpr float B_INVSCALE = 1.0f / 512.0f;

// smem: A planes: 8 x (128 rows x 128B) = 131072 ; B: 2 x (64 rows x 256B) = 32768
constexpr int SM_A      = 0;
constexpr int SM_B      = 131072;
constexpr int SM_USED   = SM_B + 2 * 16384;   // 163840
constexpr int SMEM_BYTES = SM_USED + 1024;    // alignment slack
}

// ---------------- device scratch (no runtime alloc allowed) ----------------
// g_B[k][n], k = (d-1)*512 + i  (4096 x 512 fp16, pre-scaled by 512)
__device__ __align__(128) __half g_B[KTOT * O_DIM];
__device__ float g_bias[O_DIM];

// ---------------- helpers ----------------
DI uint32_t smem_u32(const void* p) {
    uint32_t a;
    asm("{ .reg .u64 t; cvta.to.shared.u64 t, %1; cvt.u32.u64 %0, t; }" : "=r"(a) : "l"(p));
    return a;
}
DI uint32_t swz128(uint32_t off) { return off ^ ((off >> 3) & 0x70); } // 128B rows
DI uint32_t swz256(uint32_t off) { return off ^ ((off >> 4) & 0x70); } // 256B rows

DI void cpa16(uint32_t dst, const void* src) {
    asm volatile("cp.async.cg.shared.global [%0], [%1], 16;" :: "r"(dst), "l"(src) : "memory");
}
DI void cpa_commit() { asm volatile("cp.async.commit_group;" ::: "memory"); }
DI void cpa_wait1()  { asm volatile("cp.async.wait_group 1;" ::: "memory"); }
DI void cpa_wait0()  { asm volatile("cp.async.wait_group 0;" ::: "memory"); }

DI void sts128(uint32_t a, uint32_t r0, uint32_t r1, uint32_t r2, uint32_t r3) {
    asm volatile("st.shared.v4.b32 [%0], {%1,%2,%3,%4};"
                 :: "r"(a), "r"(r0), "r"(r1), "r"(r2), "r"(r3) : "memory");
}

DI void ldsm_x4(uint32_t& r0, uint32_t& r1, uint32_t& r2, uint32_t& r3, uint32_t addr) {
    asm volatile("ldmatrix.sync.aligned.m8n8.x4.shared.b16 {%0,%1,%2,%3}, [%4];"
                 : "=r"(r0), "=r"(r1), "=r"(r2), "=r"(r3) : "r"(addr));
}
DI void ldsm_x4_t(uint32_t& r0, uint32_t& r1, uint32_t& r2, uint32_t& r3, uint32_t addr) {
    asm volatile("ldmatrix.sync.aligned.m8n8.x4.trans.shared.b16 {%0,%1,%2,%3}, [%4];"
                 : "=r"(r0), "=r"(r1), "=r"(r2), "=r"(r3) : "r"(addr));
}
DI void mma16816(float& c0, float& c1, float& c2, float& c3,
                 uint32_t a0, uint32_t a1, uint32_t a2, uint32_t a3,
                 uint32_t b0, uint32_t b1) {
    asm volatile("mma.sync.aligned.m16n8k16.row.col.f32.f16.f16.f32 "
                 "{%0,%1,%2,%3}, {%4,%5,%6,%7}, {%8,%9}, {%0,%1,%2,%3};"
                 : "+f"(c0), "+f"(c1), "+f"(c2), "+f"(c3)
                 : "r"(a0), "r"(a1), "r"(a2), "r"(a3), "r"(b0), "r"(b1));
}

// ---------------- prologue: repack coeffs ----------------
// C layout: C[i][n][d], i-major, 9 floats per (i,n)
__global__ void prep_b_kernel(const float* __restrict__ C) {
    int tid = blockIdx.x * blockDim.x + threadIdx.x;   // 262144 threads, one (i,n) each
    int n = tid & (O_DIM - 1);
    int i = tid >> 9;
    const float* src = C + ((size_t)i * O_DIM + n) * 9;
    #pragma unroll
    for (int d = 1; d <= NDEG; d++)
        g_B[(size_t)((d - 1) * I_DIM + i) * O_DIM + n] = __float2half_rn(src[d] * B_SCALE);
}

// bias[n] = sum_i C[i][n][0]   (P0 == 1 plane)
__global__ void bias_kernel(const float* __restrict__ C) {
    int gw  = (blockIdx.x * blockDim.x + threadIdx.x) >> 5;  // 512 warps, one n each
    int lid = threadIdx.x & 31;
    float s = 0.f;
    for (int i = lid; i < I_DIM; i += 32)
        s += C[((size_t)i * O_DIM + gw) * 9];
    #pragma unroll
    for (int o = 16; o; o >>= 1) s += __shfl_xor_sync(0xffffffffu, s, o);
    if (lid == 0) g_bias[gw] = s;
}

// ---------------- main fused kernel ----------------
__global__ void __launch_bounds__(THREADS, 1)
legendre_main(const float* __restrict__ x, float* __restrict__ out) {
    extern __shared__ char smem_raw[];
    const uint32_t sb  = (smem_u32(smem_raw) + 1023u) & ~1023u;
    const uint32_t sbA = sb + SM_A;
    const uint32_t sbB = sb + SM_B;

    const int tid = threadIdx.x;
    const int lid = tid & 31;
    const int wid = tid >> 5;
    const int warp_m = wid & 3;        // 0..3 -> 32-row slab
    const int warp_n = wid >> 2;       // 0..1 -> 64-col slab
    const int r0 = blockIdx.x * M_TILE;
    const int n0 = blockIdx.y * N_TILE;

    // B tile prefetch: 64 rows x 256B = 1024 x 16B chunks, 4 per thread
    auto prefetch_B = [&](int t) {
        const int dd = t & 7;            // degree-1
        const int ib = t >> 3;
        const int krow0 = dd * I_DIM + ib * KBLK;
        const uint32_t dst = sbB + (t & 1) * 16384;
        #pragma unroll
        for (int q = 0; q < 4; q++) {
            int ch  = tid + q * THREADS;
            int row = ch >> 4, cc = ch & 15;
            uint32_t off = (uint32_t)row * 256 + cc * 16;
            const __half* src = g_B + (size_t)(krow0 + row) * O_DIM + n0 + cc * 8;
            cpa16(dst + swz256(off), src);
        }
        cpa_commit();
    };

    prefetch_B(0);

    // fp32 accumulators: 2 m16-tiles x 8 n8-tiles x 4
    float acc[2][8][4];
    #pragma unroll
    for (int a = 0; a < 2; a++)
        #pragma unroll
        for (int b = 0; b < 8; b++)
            #pragma unroll
            for (int c = 0; c < 4; c++) acc[a][b][c] = 0.f;

    // lane-fixed fragment address components
    const int la_row = lid & 15;
    const int la_hi  = lid >> 4;

    for (int ib = 0; ib < NUM_IB; ib++) {
        // ---- generate A planes for this i-block: tanh + Legendre recurrence ----
        {
            const int row   = tid >> 1;
            const int ihalf = (tid & 1) * 32;
            const float* xr = x + (size_t)(r0 + row) * I_DIM + ib * KBLK + ihalf;
            #pragma unroll
            for (int c = 0; c < 4; c++) {
                float4 v0 = reinterpret_cast<const float4*>(xr + c * 8)[0];
                float4 v1 = reinterpret_cast<const float4*>(xr + c * 8)[1];
                float t[8], pm1[8], pm2[8];
                t[0] = tanhf(v0.x); t[1] = tanhf(v0.y); t[2] = tanhf(v0.z); t[3] = tanhf(v0.w);
                t[4] = tanhf(v1.x); t[5] = tanhf(v1.y); t[6] = tanhf(v1.z); t[7] = tanhf(v1.w);
                const uint32_t aoff = swz128((uint32_t)row * 128 + (ihalf + c * 8) * 2);
                #pragma unroll
                for (int e = 0; e < 8; e++) { pm2[e] = 1.f; pm1[e] = t[e]; }
                #pragma unroll
                for (int d = 1; d <= NDEG; d++) {
                    float pc[8];
                    if (d == 1) {
                        #pragma unroll
                        for (int e = 0; e < 8; e++) pc[e] = pm1[e];
                    } else {
                        const float c1 = (2.f * d - 1.f) / (float)d;
                        const float c2 = (d - 1.f) / (float)d;
                        #pragma unroll
                        for (int e = 0; e < 8; e++) pc[e] = c1 * t[e] * pm1[e] - c2 * pm2[e];
                        #pragma unroll
                        for (int e = 0; e < 8; e++) { pm2[e] = pm1[e]; pm1[e] = pc[e]; }
                    }
                    uint32_t h[4];
                    #pragma unroll
                    for (int q = 0; q < 4; q++) {
                        __half2 hh = __floats2half2_rn(pc[2 * q], pc[2 * q + 1]);
                        h[q] = *reinterpret_cast<uint32_t*>(&hh);
                    }
                    sts128(sbA + (uint32_t)(d - 1) * 16384 + aoff, h[0], h[1], h[2], h[3]);
                }
            }
        }
        __syncthreads();   // A planes visible to all warps

        // ---- 8 degree-steps of MMA against double-buffered B ----
        for (int d = 1; d <= NDEG; d++) {
            const int t = ib * NDEG + (d - 1);
            if (t + 1 < NUM_IB * NDEG) { prefetch_B(t + 1); cpa_wait1(); }
            else                       { cpa_wait0(); }
            __syncthreads();           // B(t) ready for everyone

            const uint32_t Abase = sbA + (uint32_t)(d - 1) * 16384;
            const uint32_t Bbase = sbB + (t & 1) * 16384;

            #pragma unroll
            for (int j = 0; j < 4; j++) {              // k16 steps within KBLK=64
                uint32_t a0[4], a1[4];
                {
                    uint32_t off0 = (uint32_t)(warp_m * 32 + la_row) * 128 + (j * 16 + la_hi * 8) * 2;
                    uint32_t off1 = off0 + 16 * 128;
                    ldsm_x4(a0[0], a0[1], a0[2], a0[3], Abase + swz128(off0));
                    ldsm_x4(a1[0], a1[1], a1[2], a1[3], Abase + swz128(off1));
                }
                #pragma unroll
                for (int nb = 0; nb < 4; nb++) {       // n16 chunks -> 2 n8 frags each
                    uint32_t b0, b1, b2, b3;
                    uint32_t boff = (uint32_t)(j * 16 + la_row) * 256 +
                                    (warp_n * 64 + nb * 16 + la_hi * 8) * 2;
                    ldsm_x4_t(b0, b1, b2, b3, Bbase + swz256(boff));
                    float* c00 = acc[0][2 * nb];
                    float* c01 = acc[0][2 * nb + 1];
                    float* c10 = acc[1][2 * nb];
                    float* c11 = acc[1][2 * nb + 1];
                    mma16816(c00[0], c00[1], c00[2], c00[3], a0[0], a0[1], a0[2], a0[3], b0, b1);
                    mma16816(c01[0], c01[1], c01[2], c01[3], a0[0], a0[1], a0[2], a0[3], b2, b3);
                    mma16816(c10[0], c10[1], c10[2], c10[3], a1[0], a1[1], a1[2], a1[3], b0, b1);
                    mma16816(c11[0], c11[1], c11[2], c11[3], a1[0], a1[1], a1[2], a1[3], b2, b3);
                }
            }
            __syncthreads();           // all warps done with B(t) before buffer reuse
        }
    }

    // ---- epilogue: unscale, add d=0 bias, store fp32 ----
    {
        const int g   = lid >> 2;      // row group
        const int tg  = lid & 3;       // col pair
        #pragma unroll
        for (int mt = 0; mt < 2; mt++) {
            const int rbase = r0 + warp_m * 32 + mt * 16 + g;
            #pragma unroll
            for (int nt = 0; nt < 8; nt++) {
                const int col = n0 + warp_n * 64 + nt * 8 + tg * 2;
                const float bz0 = g_bias[col];
                const float bz1 = g_bias[col + 1];
                float2 v;
                v.x = acc[mt][nt][0] * B_INVSCALE + bz0;
                v.y = acc[mt][nt][1] * B_INVSCALE + bz1;
                *reinterpret_cast<float2*>(out + (size_t)rbase * O_DIM + col) = v;
                v.x = acc[mt][nt][2] * B_INVSCALE + bz0;
                v.y = acc[mt][nt][3] * B_INVSCALE + bz1;
                *reinterpret_cast<float2*>(out + (size_t)(rbase + 8) * O_DIM + col) = v;
            }
        }
    }
}

// ---------------- launch ----------------
extern "C" void kernel_launch(void* const* d_in, const int* in_sizes, int n_in,
                              void* d_out, int out_size) {
    const float* x = (const float*)d_in[0];
    const float* C = (const float*)d_in[1];
    float* out = (float*)d_out;

    prep_b_kernel<<<(I_DIM * O_DIM) / 256, 256>>>(C);
    bias_kernel<<<(O_DIM * 32) / 256, 256>>>(C);

    cudaFuncSetAttribute(legendre_main, cudaFuncAttributeMaxDynamicSharedMemorySize, SMEM_BYTES);
    dim3 grid(16384 / M_TILE, O_DIM / N_TILE);
    legendre_main<<<grid, THREADS, SMEM_BYTES>>>(x, out);
}